// round 3
// baseline (speedup 1.0000x reference)
#include <cuda_runtime.h>

#define HIDDEN 768
#define HEADS 12
#define HD 64
#define BB 8
#define LQ 512
#define LK 1024
#define QT 32
#define QPAD 65
#define KPAD 68

// Scratch (allocation-free rule: __device__ globals)
__device__ float g_q[BB * LQ * HIDDEN];
__device__ float g_k[BB * LK * HIDDEN];
__device__ float g_v[BB * LK * HIDDEN];
__device__ float g_ctx[BB * LQ * HIDDEN];
__device__ float g_tmp[BB * LQ * HIDDEN];

// C[M,N] = A[M,K] @ Bm[N,K]^T + bias[N] (+ resid[M,N])
// 64x64 tile, 256 threads, 4x4 per thread, BK=16. M,N,K multiples of 64/16.
__global__ void gemm_nt(const float* __restrict__ A, const float* __restrict__ Bm,
                        const float* __restrict__ bias, const float* __restrict__ resid,
                        float* __restrict__ C, int M, int N, int K)
{
    __shared__ float As[16][68];
    __shared__ float Bs[16][68];
    const int tid = threadIdx.x;
    const int tx = tid & 15, ty = tid >> 4;
    const int row0 = blockIdx.y * 64, col0 = blockIdx.x * 64;
    const int lr = tid >> 2;          // 0..63
    const int lc = (tid & 3) * 4;     // 0,4,8,12

    float acc[4][4] = {};

    for (int k0 = 0; k0 < K; k0 += 16) {
        float4 a = *(const float4*)(A  + (size_t)(row0 + lr) * K + k0 + lc);
        float4 b = *(const float4*)(Bm + (size_t)(col0 + lr) * K + k0 + lc);
        __syncthreads();
        As[lc + 0][lr] = a.x; As[lc + 1][lr] = a.y; As[lc + 2][lr] = a.z; As[lc + 3][lr] = a.w;
        Bs[lc + 0][lr] = b.x; Bs[lc + 1][lr] = b.y; Bs[lc + 2][lr] = b.z; Bs[lc + 3][lr] = b.w;
        __syncthreads();
        #pragma unroll
        for (int kk = 0; kk < 16; kk++) {
            float av[4], bv[4];
            *(float4*)av = *(const float4*)&As[kk][ty * 4];
            *(float4*)bv = *(const float4*)&Bs[kk][tx * 4];
            #pragma unroll
            for (int i = 0; i < 4; i++)
                #pragma unroll
                for (int j = 0; j < 4; j++)
                    acc[i][j] += av[i] * bv[j];
        }
    }

    const int c = col0 + tx * 4;
    float4 bb4 = *(const float4*)(bias + c);
    #pragma unroll
    for (int i = 0; i < 4; i++) {
        const int r = row0 + ty * 4 + i;
        float4 o;
        o.x = acc[i][0] + bb4.x;
        o.y = acc[i][1] + bb4.y;
        o.z = acc[i][2] + bb4.z;
        o.w = acc[i][3] + bb4.w;
        if (resid) {
            float4 rv = *(const float4*)(resid + (size_t)r * N + c);
            o.x += rv.x; o.y += rv.y; o.z += rv.z; o.w += rv.w;
        }
        *(float4*)(C + (size_t)r * N + c) = o;
    }
}

// Fused attention per (q-tile of 32 rows, head, batch):
// scores (QK^T/8 + mask) -> softmax -> write probs -> ctx = P@V
__global__ void attn_kernel(const float* __restrict__ Qp, const float* __restrict__ Kp,
                            const float* __restrict__ Vp, const float* __restrict__ mask,
                            float* __restrict__ probs, float* __restrict__ ctx)
{
    extern __shared__ float smem[];
    float* Sm     = smem;                       // QT*LK
    float* Qs     = Sm + QT * LK;               // QT*QPAD
    float* KVs    = Qs + QT * QPAD;             // 64*KPAD
    float* rowinv = KVs + 64 * KPAD;            // QT

    const int tid = threadIdx.x;
    const int q0 = blockIdx.x * QT;
    const int h  = blockIdx.y;
    const int b  = blockIdx.z;

    // Load Q tile [QT][64]
    for (int idx = tid; idx < QT * HD; idx += 256) {
        int r = idx >> 6, d = idx & 63;
        Qs[r * QPAD + d] = Qp[(size_t)(b * LQ + q0 + r) * HIDDEN + h * HD + d];
    }

    const int rg = tid >> 4;   // 0..15 -> rows rg*2, rg*2+1
    const int cg = tid & 15;   // 0..15 -> 4 cols
    const int r0 = rg * 2;

    // ---- scores ----
    for (int c0 = 0; c0 < LK; c0 += 64) {
        __syncthreads();
        for (int idx = tid; idx < 64 * HD; idx += 256) {
            int r = idx >> 6, d = idx & 63;
            KVs[d * KPAD + r] = Kp[(size_t)(b * LK + c0 + r) * HIDDEN + h * HD + d];
        }
        __syncthreads();
        float acc[2][4] = {};
        #pragma unroll 4
        for (int kk = 0; kk < HD; kk++) {
            float qa = Qs[r0 * QPAD + kk];
            float qb = Qs[(r0 + 1) * QPAD + kk];
            float kv[4];
            *(float4*)kv = *(const float4*)&KVs[kk * KPAD + cg * 4];
            #pragma unroll
            for (int j = 0; j < 4; j++) {
                acc[0][j] += qa * kv[j];
                acc[1][j] += qb * kv[j];
            }
        }
        #pragma unroll
        for (int i = 0; i < 2; i++)
            #pragma unroll
            for (int j = 0; j < 4; j++) {
                int c = c0 + cg * 4 + j;
                Sm[(r0 + i) * LK + c] = acc[i][j] * 0.125f + mask[b * LK + c];
            }
    }
    __syncthreads();

    // ---- softmax: warp w owns rows 4w..4w+3 ----
    {
        const int w = tid >> 5, lane = tid & 31;
        for (int rr = 0; rr < 4; rr++) {
            int r = w * 4 + rr;
            float m = -1e30f;
            for (int c = lane; c < LK; c += 32) m = fmaxf(m, Sm[r * LK + c]);
            #pragma unroll
            for (int off = 16; off; off >>= 1) m = fmaxf(m, __shfl_xor_sync(0xffffffffu, m, off));
            float s = 0.f;
            for (int c = lane; c < LK; c += 32) {
                float e = __expf(Sm[r * LK + c] - m);
                Sm[r * LK + c] = e;
                s += e;
            }
            #pragma unroll
            for (int off = 16; off; off >>= 1) s += __shfl_xor_sync(0xffffffffu, s, off);
            if (lane == 0) rowinv[r] = 1.f / s;
        }
    }
    __syncthreads();

    // ---- normalize + write probs (coalesced) ----
    {
        float* prow = probs + ((size_t)((b * HEADS + h) * LQ + q0)) * LK;
        for (int idx = tid; idx < QT * LK; idx += 256) {
            float p = Sm[idx] * rowinv[idx >> 10];
            Sm[idx] = p;
            prow[idx] = p;
        }
    }

    // ---- ctx = P @ V ----
    float acc[2][4] = {};
    for (int c0 = 0; c0 < LK; c0 += 64) {
        __syncthreads();
        for (int idx = tid; idx < 64 * HD; idx += 256) {
            int r = idx >> 6, d = idx & 63;
            KVs[r * KPAD + d] = Vp[(size_t)(b * LK + c0 + r) * HIDDEN + h * HD + d];
        }
        __syncthreads();
        #pragma unroll 4
        for (int kk = 0; kk < 64; kk++) {
            float p0 = Sm[r0 * LK + c0 + kk];
            float p1 = Sm[(r0 + 1) * LK + c0 + kk];
            float vv[4];
            *(float4*)vv = *(const float4*)&KVs[kk * KPAD + cg * 4];
            #pragma unroll
            for (int j = 0; j < 4; j++) {
                acc[0][j] += p0 * vv[j];
                acc[1][j] += p1 * vv[j];
            }
        }
    }
    #pragma unroll
    for (int i = 0; i < 2; i++)
        #pragma unroll
        for (int j = 0; j < 4; j++)
            ctx[(size_t)(b * LQ + q0 + r0 + i) * HIDDEN + h * HD + cg * 4 + j] = acc[i][j];
}

// Row LayerNorm over 768; one block of 256 threads per row.
__global__ void out_ln(const float* __restrict__ X, const float* __restrict__ gamma,
                       const float* __restrict__ beta, float* __restrict__ out)
{
    const int row = blockIdx.x;
    const int tid = threadIdx.x;
    const float* x = X + (size_t)row * HIDDEN;

    float v[3];
    float s = 0.f, s2 = 0.f;
    #pragma unroll
    for (int i = 0; i < 3; i++) {
        v[i] = x[tid + i * 256];
        s += v[i];
        s2 += v[i] * v[i];
    }
    const int w = tid >> 5, lane = tid & 31;
    #pragma unroll
    for (int off = 16; off; off >>= 1) {
        s  += __shfl_xor_sync(0xffffffffu, s,  off);
        s2 += __shfl_xor_sync(0xffffffffu, s2, off);
    }
    __shared__ float rs[8], rs2[8];
    __shared__ float mu_s, inv_s;
    if (lane == 0) { rs[w] = s; rs2[w] = s2; }
    __syncthreads();
    if (tid == 0) {
        float S = 0.f, S2 = 0.f;
        #pragma unroll
        for (int i = 0; i < 8; i++) { S += rs[i]; S2 += rs2[i]; }
        float mu = S * (1.0f / HIDDEN);
        float var = S2 * (1.0f / HIDDEN) - mu * mu;
        mu_s = mu;
        inv_s = rsqrtf(var + 1e-12f);
    }
    __syncthreads();
    const float mu = mu_s, inv = inv_s;
    #pragma unroll
    for (int i = 0; i < 3; i++) {
        int c = tid + i * 256;
        out[(size_t)row * HIDDEN + c] = (v[i] - mu) * inv * gamma[c] + beta[c];
    }
}

extern "C" void kernel_launch(void* const* d_in, const int* in_sizes, int n_in,
                              void* d_out, int out_size)
{
    const float* query = (const float*)d_in[0];
    const float* key   = (const float*)d_in[1];
    const float* value = (const float*)d_in[2];
    const float* mask  = (const float*)d_in[3];
    // d_in[4] = q_attention_mask (unused by reference math)
    const float* Wq = (const float*)d_in[5];
    const float* bq = (const float*)d_in[6];
    const float* Wk = (const float*)d_in[7];
    const float* bk = (const float*)d_in[8];
    const float* Wv = (const float*)d_in[9];
    const float* bv = (const float*)d_in[10];
    const float* Wo = (const float*)d_in[11];
    const float* bo = (const float*)d_in[12];
    const float* gamma = (const float*)d_in[13];
    const float* beta  = (const float*)d_in[14];

    float* out   = (float*)d_out;
    float* probs = out + (size_t)BB * LQ * HIDDEN;

    float *qp, *kp, *vp, *ctx, *tmp;
    cudaGetSymbolAddress((void**)&qp,  g_q);
    cudaGetSymbolAddress((void**)&kp,  g_k);
    cudaGetSymbolAddress((void**)&vp,  g_v);
    cudaGetSymbolAddress((void**)&ctx, g_ctx);
    cudaGetSymbolAddress((void**)&tmp, g_tmp);

    // Q/K/V projections
    gemm_nt<<<dim3(HIDDEN / 64, (BB * LQ) / 64), 256>>>(query, Wq, bq, nullptr, qp, BB * LQ, HIDDEN, HIDDEN);
    gemm_nt<<<dim3(HIDDEN / 64, (BB * LK) / 64), 256>>>(key,   Wk, bk, nullptr, kp, BB * LK, HIDDEN, HIDDEN);
    gemm_nt<<<dim3(HIDDEN / 64, (BB * LK) / 64), 256>>>(value, Wv, bv, nullptr, vp, BB * LK, HIDDEN, HIDDEN);

    // Fused attention
    size_t smem = (size_t)(QT * LK + QT * QPAD + 64 * KPAD + QT) * sizeof(float);
    cudaFuncSetAttribute(attn_kernel, cudaFuncAttributeMaxDynamicSharedMemorySize, (int)smem);
    attn_kernel<<<dim3(LQ / QT, HEADS, BB), 256, smem>>>(qp, kp, vp, mask, probs, ctx);

    // Output projection + bias + residual, then LayerNorm
    gemm_nt<<<dim3(HIDDEN / 64, (BB * LQ) / 64), 256>>>(ctx, Wo, bo, query, tmp, BB * LQ, HIDDEN, HIDDEN);
    out_ln<<<BB * LQ, 256>>>(tmp, gamma, beta, out);
}

// round 5
// speedup vs baseline: 1.2260x; 1.2260x over previous
#include <cuda_runtime.h>

#define HIDDEN 768
#define HEADS 12
#define HD 64
#define BB 8
#define LQ 512
#define LK 1024
#define QT 32
#define QPAD 65
#define KPAD 68

#define BM 128
#define BN 128
#define BKG 16

// Scratch (allocation-free rule: __device__ globals)
__device__ float g_q[BB * LQ * HIDDEN];
__device__ float g_k[BB * LK * HIDDEN];
__device__ float g_v[BB * LK * HIDDEN];
__device__ float g_ctx[BB * LQ * HIDDEN];
__device__ float g_tmp[BB * LQ * HIDDEN];

// ---- packed fp32x2 helpers (Blackwell FFMA2) ----
__device__ __forceinline__ void fma2(unsigned long long& d, unsigned long long a, unsigned long long b)
{
    asm("fma.rn.f32x2 %0, %1, %2, %3;" : "=l"(d) : "l"(a), "l"(b), "l"(d));
}
__device__ __forceinline__ unsigned long long dup2(float x)
{
    unsigned long long r;
    asm("mov.b64 %0, {%1, %1};" : "=l"(r) : "r"(__float_as_uint(x)));
    return r;
}
union F4U2 { float4 f4; unsigned long long u[2]; };
union U2F2 { unsigned long long u; float f[2]; };

// C[M,N] = A[M,K] @ Bm[N,K]^T + bias[N] (+ resid[M,N])
// 128x128 tile, 256 threads, 8x8 per thread via f32x2, BK=16, reg-prefetch pipeline.
__global__ __launch_bounds__(256) void gemm_nt(
    const float* __restrict__ A, const float* __restrict__ Bm,
    const float* __restrict__ bias, const float* __restrict__ resid,
    float* __restrict__ C, int M, int N, int K)
{
    __shared__ float As[BKG][BM + 4];
    __shared__ float Bs[BKG][BN + 4];
    const int tid = threadIdx.x;
    const int tx = tid & 15;         // col group: 8 cols each
    const int ty = tid >> 4;         // row group: 8 rows each
    const int row0 = blockIdx.y * BM, col0 = blockIdx.x * BN;

    const int lr = tid >> 2;         // 0..63
    const int lc = (tid & 3) * 4;    // 0,4,8,12
    const float* Aptr = A  + (size_t)(row0 + lr) * K + lc;
    const float* Bptr = Bm + (size_t)(col0 + lr) * K + lc;

    float4 pa0 = *(const float4*)(Aptr);
    float4 pa1 = *(const float4*)(Aptr + (size_t)64 * K);
    float4 pb0 = *(const float4*)(Bptr);
    float4 pb1 = *(const float4*)(Bptr + (size_t)64 * K);

    unsigned long long acc[8][4];
    #pragma unroll
    for (int i = 0; i < 8; i++)
        #pragma unroll
        for (int j = 0; j < 4; j++) acc[i][j] = 0ull;

    for (int k0 = 0; k0 < K; k0 += BKG) {
        __syncthreads();
        As[lc + 0][lr] = pa0.x; As[lc + 1][lr] = pa0.y; As[lc + 2][lr] = pa0.z; As[lc + 3][lr] = pa0.w;
        As[lc + 0][lr + 64] = pa1.x; As[lc + 1][lr + 64] = pa1.y; As[lc + 2][lr + 64] = pa1.z; As[lc + 3][lr + 64] = pa1.w;
        Bs[lc + 0][lr] = pb0.x; Bs[lc + 1][lr] = pb0.y; Bs[lc + 2][lr] = pb0.z; Bs[lc + 3][lr] = pb0.w;
        Bs[lc + 0][lr + 64] = pb1.x; Bs[lc + 1][lr + 64] = pb1.y; Bs[lc + 2][lr + 64] = pb1.z; Bs[lc + 3][lr + 64] = pb1.w;
        __syncthreads();

        const int kn = k0 + BKG;
        if (kn < K) {
            pa0 = *(const float4*)(Aptr + kn);
            pa1 = *(const float4*)(Aptr + (size_t)64 * K + kn);
            pb0 = *(const float4*)(Bptr + kn);
            pb1 = *(const float4*)(Bptr + (size_t)64 * K + kn);
        }

        #pragma unroll
        for (int kk = 0; kk < BKG; kk++) {
            float4 a0 = *(const float4*)&As[kk][ty * 8];
            float4 a1 = *(const float4*)&As[kk][ty * 8 + 4];
            F4U2 b0, b1;
            b0.f4 = *(const float4*)&Bs[kk][tx * 8];
            b1.f4 = *(const float4*)&Bs[kk][tx * 8 + 4];
            unsigned long long ad[8];
            ad[0] = dup2(a0.x); ad[1] = dup2(a0.y); ad[2] = dup2(a0.z); ad[3] = dup2(a0.w);
            ad[4] = dup2(a1.x); ad[5] = dup2(a1.y); ad[6] = dup2(a1.z); ad[7] = dup2(a1.w);
            #pragma unroll
            for (int i = 0; i < 8; i++) {
                fma2(acc[i][0], ad[i], b0.u[0]);
                fma2(acc[i][1], ad[i], b0.u[1]);
                fma2(acc[i][2], ad[i], b1.u[0]);
                fma2(acc[i][3], ad[i], b1.u[1]);
            }
        }
    }

    const int c = col0 + tx * 8;
    float4 bb0 = *(const float4*)(bias + c);
    float4 bb1 = *(const float4*)(bias + c + 4);
    #pragma unroll
    for (int i = 0; i < 8; i++) {
        const int r = row0 + ty * 8 + i;
        U2F2 u0, u1, u2, u3;
        u0.u = acc[i][0]; u1.u = acc[i][1]; u2.u = acc[i][2]; u3.u = acc[i][3];
        float4 o0, o1;
        o0.x = u0.f[0] + bb0.x; o0.y = u0.f[1] + bb0.y;
        o0.z = u1.f[0] + bb0.z; o0.w = u1.f[1] + bb0.w;
        o1.x = u2.f[0] + bb1.x; o1.y = u2.f[1] + bb1.y;
        o1.z = u3.f[0] + bb1.z; o1.w = u3.f[1] + bb1.w;
        if (resid) {
            float4 r0v = *(const float4*)(resid + (size_t)r * N + c);
            float4 r1v = *(const float4*)(resid + (size_t)r * N + c + 4);
            o0.x += r0v.x; o0.y += r0v.y; o0.z += r0v.z; o0.w += r0v.w;
            o1.x += r1v.x; o1.y += r1v.y; o1.z += r1v.z; o1.w += r1v.w;
        }
        *(float4*)(C + (size_t)r * N + c) = o0;
        *(float4*)(C + (size_t)r * N + c + 4) = o1;
    }
}

// Fused attention per (q-tile of 32 rows, head, batch):
// scores (QK^T/8 + mask) -> softmax -> write probs -> ctx = P@V
__global__ void attn_kernel(const float* __restrict__ Qp, const float* __restrict__ Kp,
                            const float* __restrict__ Vp, const float* __restrict__ mask,
                            float* __restrict__ probs, float* __restrict__ ctx)
{
    extern __shared__ float smem[];
    float* Sm     = smem;                       // QT*LK
    float* Qs     = Sm + QT * LK;               // QT*QPAD
    float* KVs    = Qs + QT * QPAD;             // 64*KPAD
    float* rowinv = KVs + 64 * KPAD;            // QT

    const int tid = threadIdx.x;
    const int q0 = blockIdx.x * QT;
    const int h  = blockIdx.y;
    const int b  = blockIdx.z;

    // Load Q tile [QT][64]
    for (int idx = tid; idx < QT * HD; idx += 256) {
        int r = idx >> 6, d = idx & 63;
        Qs[r * QPAD + d] = Qp[(size_t)(b * LQ + q0 + r) * HIDDEN + h * HD + d];
    }

    const int rg = tid >> 4;   // 0..15 -> rows rg*2, rg*2+1
    const int cg = tid & 15;   // 0..15 -> 4 cols
    const int r0 = rg * 2;

    // ---- scores ----
    for (int c0 = 0; c0 < LK; c0 += 64) {
        __syncthreads();
        for (int idx = tid; idx < 64 * HD; idx += 256) {
            int r = idx >> 6, d = idx & 63;
            KVs[d * KPAD + r] = Kp[(size_t)(b * LK + c0 + r) * HIDDEN + h * HD + d];
        }
        __syncthreads();
        unsigned long long acc2[2][2] = {0ull, 0ull, 0ull, 0ull};
        #pragma unroll 8
        for (int kk = 0; kk < HD; kk++) {
            unsigned long long qa = dup2(Qs[r0 * QPAD + kk]);
            unsigned long long qb = dup2(Qs[(r0 + 1) * QPAD + kk]);
            F4U2 kv;
            kv.f4 = *(const float4*)&KVs[kk * KPAD + cg * 4];
            fma2(acc2[0][0], qa, kv.u[0]);
            fma2(acc2[0][1], qa, kv.u[1]);
            fma2(acc2[1][0], qb, kv.u[0]);
            fma2(acc2[1][1], qb, kv.u[1]);
        }
        #pragma unroll
        for (int i = 0; i < 2; i++) {
            U2F2 lo, hi;
            lo.u = acc2[i][0]; hi.u = acc2[i][1];
            int c = c0 + cg * 4;
            Sm[(r0 + i) * LK + c + 0] = lo.f[0] * 0.125f + mask[b * LK + c + 0];
            Sm[(r0 + i) * LK + c + 1] = lo.f[1] * 0.125f + mask[b * LK + c + 1];
            Sm[(r0 + i) * LK + c + 2] = hi.f[0] * 0.125f + mask[b * LK + c + 2];
            Sm[(r0 + i) * LK + c + 3] = hi.f[1] * 0.125f + mask[b * LK + c + 3];
        }
    }
    __syncthreads();

    // ---- softmax: warp w owns rows 4w..4w+3 ----
    {
        const int w = tid >> 5, lane = tid & 31;
        for (int rr = 0; rr < 4; rr++) {
            int r = w * 4 + rr;
            float m = -1e30f;
            for (int c = lane; c < LK; c += 32) m = fmaxf(m, Sm[r * LK + c]);
            #pragma unroll
            for (int off = 16; off; off >>= 1) m = fmaxf(m, __shfl_xor_sync(0xffffffffu, m, off));
            float s = 0.f;
            for (int c = lane; c < LK; c += 32) {
                float e = __expf(Sm[r * LK + c] - m);
                Sm[r * LK + c] = e;
                s += e;
            }
            #pragma unroll
            for (int off = 16; off; off >>= 1) s += __shfl_xor_sync(0xffffffffu, s, off);
            if (lane == 0) rowinv[r] = 1.f / s;
        }
    }
    __syncthreads();

    // ---- normalize + write probs (coalesced) ----
    {
        float* prow = probs + ((size_t)((b * HEADS + h) * LQ + q0)) * LK;
        for (int idx = tid; idx < QT * LK; idx += 256) {
            float p = Sm[idx] * rowinv[idx >> 10];
            Sm[idx] = p;
            prow[idx] = p;
        }
    }

    // ---- ctx = P @ V ----
    unsigned long long acc2[2][2] = {0ull, 0ull, 0ull, 0ull};
    for (int c0 = 0; c0 < LK; c0 += 64) {
        __syncthreads();
        for (int idx = tid; idx < 64 * HD; idx += 256) {
            int r = idx >> 6, d = idx & 63;
            KVs[r * KPAD + d] = Vp[(size_t)(b * LK + c0 + r) * HIDDEN + h * HD + d];
        }
        __syncthreads();
        #pragma unroll 8
        for (int kk = 0; kk < 64; kk++) {
            unsigned long long p0 = dup2(Sm[r0 * LK + c0 + kk]);
            unsigned long long p1 = dup2(Sm[(r0 + 1) * LK + c0 + kk]);
            F4U2 vv;
            vv.f4 = *(const float4*)&KVs[kk * KPAD + cg * 4];
            fma2(acc2[0][0], p0, vv.u[0]);
            fma2(acc2[0][1], p0, vv.u[1]);
            fma2(acc2[1][0], p1, vv.u[0]);
            fma2(acc2[1][1], p1, vv.u[1]);
        }
    }
    #pragma unroll
    for (int i = 0; i < 2; i++) {
        U2F2 lo, hi;
        lo.u = acc2[i][0]; hi.u = acc2[i][1];
        float4 o;
        o.x = lo.f[0]; o.y = lo.f[1]; o.z = hi.f[0]; o.w = hi.f[1];
        *(float4*)(ctx + (size_t)(b * LQ + q0 + r0 + i) * HIDDEN + h * HD + cg * 4) = o;
    }
}

// Row LayerNorm over 768; one block of 256 threads per row.
__global__ void out_ln(const float* __restrict__ X, const float* __restrict__ gamma,
                       const float* __restrict__ beta, float* __restrict__ out)
{
    const int row = blockIdx.x;
    const int tid = threadIdx.x;
    const float* x = X + (size_t)row * HIDDEN;

    float v[3];
    float s = 0.f, s2 = 0.f;
    #pragma unroll
    for (int i = 0; i < 3; i++) {
        v[i] = x[tid + i * 256];
        s += v[i];
        s2 += v[i] * v[i];
    }
    const int w = tid >> 5, lane = tid & 31;
    #pragma unroll
    for (int off = 16; off; off >>= 1) {
        s  += __shfl_xor_sync(0xffffffffu, s,  off);
        s2 += __shfl_xor_sync(0xffffffffu, s2, off);
    }
    __shared__ float rs[8], rs2[8];
    __shared__ float mu_s, inv_s;
    if (lane == 0) { rs[w] = s; rs2[w] = s2; }
    __syncthreads();
    if (tid == 0) {
        float S = 0.f, S2 = 0.f;
        #pragma unroll
        for (int i = 0; i < 8; i++) { S += rs[i]; S2 += rs2[i]; }
        float mu = S * (1.0f / HIDDEN);
        float var = S2 * (1.0f / HIDDEN) - mu * mu;
        mu_s = mu;
        inv_s = rsqrtf(var + 1e-12f);
    }
    __syncthreads();
    const float mu = mu_s, inv = inv_s;
    #pragma unroll
    for (int i = 0; i < 3; i++) {
        int c = tid + i * 256;
        out[(size_t)row * HIDDEN + c] = (v[i] - mu) * inv * gamma[c] + beta[c];
    }
}

extern "C" void kernel_launch(void* const* d_in, const int* in_sizes, int n_in,
                              void* d_out, int out_size)
{
    const float* query = (const float*)d_in[0];
    const float* key   = (const float*)d_in[1];
    const float* value = (const float*)d_in[2];
    const float* mask  = (const float*)d_in[3];
    // d_in[4] = q_attention_mask (unused by reference math)
    const float* Wq = (const float*)d_in[5];
    const float* bq = (const float*)d_in[6];
    const float* Wk = (const float*)d_in[7];
    const float* bk = (const float*)d_in[8];
    const float* Wv = (const float*)d_in[9];
    const float* bv = (const float*)d_in[10];
    const float* Wo = (const float*)d_in[11];
    const float* bo = (const float*)d_in[12];
    const float* gamma = (const float*)d_in[13];
    const float* beta  = (const float*)d_in[14];

    float* out   = (float*)d_out;
    float* probs = out + (size_t)BB * LQ * HIDDEN;

    float *qp, *kp, *vp, *ctx, *tmp;
    cudaGetSymbolAddress((void**)&qp,  g_q);
    cudaGetSymbolAddress((void**)&kp,  g_k);
    cudaGetSymbolAddress((void**)&vp,  g_v);
    cudaGetSymbolAddress((void**)&ctx, g_ctx);
    cudaGetSymbolAddress((void**)&tmp, g_tmp);

    // Q/K/V projections
    gemm_nt<<<dim3(HIDDEN / BN, (BB * LQ) / BM), 256>>>(query, Wq, bq, nullptr, qp, BB * LQ, HIDDEN, HIDDEN);
    gemm_nt<<<dim3(HIDDEN / BN, (BB * LK) / BM), 256>>>(key,   Wk, bk, nullptr, kp, BB * LK, HIDDEN, HIDDEN);
    gemm_nt<<<dim3(HIDDEN / BN, (BB * LK) / BM), 256>>>(value, Wv, bv, nullptr, vp, BB * LK, HIDDEN, HIDDEN);

    // Fused attention
    size_t smem = (size_t)(QT * LK + QT * QPAD + 64 * KPAD + QT) * sizeof(float);
    cudaFuncSetAttribute(attn_kernel, cudaFuncAttributeMaxDynamicSharedMemorySize, (int)smem);
    attn_kernel<<<dim3(LQ / QT, HEADS, BB), 256, smem>>>(qp, kp, vp, mask, probs, ctx);

    // Output projection + bias + residual, then LayerNorm
    gemm_nt<<<dim3(HIDDEN / BN, (BB * LQ) / BM), 256>>>(ctx, Wo, bo, query, tmp, BB * LQ, HIDDEN, HIDDEN);
    out_ln<<<BB * LQ, 256>>>(tmp, gamma, beta, out);
}